// round 12
// baseline (speedup 1.0000x reference)
#include <cuda_runtime.h>
#include <cuda_fp16.h>
#include <math.h>
#include <stdint.h>

#define NTOK 65536
#define DDIM 128
#define NEXP 16
#define TOPK 3

#define KPAD 136              // fp16 per padded row
#define ROWB 272              // bytes per padded row (16B-aligned, bank stride 4)
#define GEMM_GX 18            // 16*18=288 CTAs ~= one wave at 2 CTAs/SM

// ---------------------------------------------------------------------------
// Device globals
// ---------------------------------------------------------------------------
__device__ int      g_cnt[NEXP];
__device__ unsigned g_list[NEXP * NTOK];                 // (token<<2)|slot
__device__ float    g_wlist[NEXP * NTOK];
__device__ __half   g_Bh[NEXP * DDIM * KPAD];            // fp16 We^T, padded rows
__device__ __half   g_xh[(size_t)NTOK * DDIM];           // fp16 image of x (16MB)
__device__ __half   g_ybuf[(size_t)NTOK * TOPK * DDIM];  // fp16 partials (24MB)
__device__ uint4    g_topk[NTOK];
__device__ float    g_part[512 * NEXP];

// ---------------------------------------------------------------------------
// helpers
// ---------------------------------------------------------------------------
__device__ __forceinline__ uint32_t smem_u32(const void* p) {
    uint32_t a;
    asm("{ .reg .u64 t; cvta.to.shared.u64 t, %1; cvt.u32.u64 %0, t; }" : "=r"(a) : "l"(p));
    return a;
}

__device__ __forceinline__ void cp_async16(uint32_t dst, const void* src, uint32_t sz) {
    asm volatile("cp.async.ca.shared.global [%0], [%1], 16, %2;"
                 :: "r"(dst), "l"(src), "r"(sz) : "memory");
}

#define CP_COMMIT() asm volatile("cp.async.commit_group;" ::: "memory")

#define LDSM_X4(r0, r1, r2, r3, addr) \
    asm volatile("ldmatrix.sync.aligned.m8n8.x4.shared.b16 {%0,%1,%2,%3}, [%4];" \
                 : "=r"(r0), "=r"(r1), "=r"(r2), "=r"(r3) : "r"(addr))

__device__ __forceinline__ void mma16816(float* c,
    uint32_t a0, uint32_t a1, uint32_t a2, uint32_t a3, uint32_t b0, uint32_t b1)
{
    asm volatile(
        "mma.sync.aligned.m16n8k16.row.col.f32.f16.f16.f32 "
        "{%0,%1,%2,%3}, {%4,%5,%6,%7}, {%8,%9}, {%0,%1,%2,%3};"
        : "+f"(c[0]), "+f"(c[1]), "+f"(c[2]), "+f"(c[3])
        : "r"(a0), "r"(a1), "r"(a2), "r"(a3), "r"(b0), "r"(b1));
}

// ---------------------------------------------------------------------------
// prep: blocks [0,8192) convert x -> fp16; blocks [8192,8256) build padded
// fp16 We^T images; block 0 zeroes g_cnt.
// ---------------------------------------------------------------------------
__global__ void __launch_bounds__(256) prep_kernel(
    const float* __restrict__ x, const float* __restrict__ We)
{
    int bid = blockIdx.x, tid = threadIdx.x;
    if (bid < 8192) {
        if (bid == 0 && tid < NEXP) g_cnt[tid] = 0;
        size_t i = (size_t)bid * 256 + tid;          // over NTOK*DDIM/4
        float4 v = ((const float4*)x)[i];
        __half2 h0, h1;
        h0.x = __float2half(v.x); h0.y = __float2half(v.y);
        h1.x = __float2half(v.z); h1.y = __float2half(v.w);
        uint2 st;
        st.x = *(uint32_t*)&h0;
        st.y = *(uint32_t*)&h1;
        *(uint2*)(g_xh + i * 4) = st;
    } else {
        int eb = bid - 8192;                          // 0..63
        int e = eb >> 2, q = eb & 3;
        const float* W = We + (size_t)e * DDIM * DDIM;
        __half* dst = g_Bh + (size_t)e * DDIM * KPAD;
        int i0 = q * 2048 + tid;
        for (int i = i0; i < (q + 1) * 2048; i += 256) {
            int n = i >> 6, kp = i & 63, k = kp * 2;
            __half2 hp;
            hp.x = __float2half(W[k * DDIM + n]);
            hp.y = __float2half(W[(k + 1) * DDIM + n]);
            *(__half2*)(dst + n * KPAD + k) = hp;
        }
    }
}

// ---------------------------------------------------------------------------
// Gating (unchanged)
// ---------------------------------------------------------------------------
__global__ void __launch_bounds__(128) gating_kernel(
    const float* __restrict__ x, const float* __restrict__ noise,
    const float* __restrict__ Wg, const float* __restrict__ bg,
    const float* __restrict__ Wn, const float* __restrict__ bn,
    float* __restrict__ comb)
{
    __shared__ float WgT[NEXP * DDIM];
    __shared__ float WnT[NEXP * DDIM];
    __shared__ float tw[128][3];
    __shared__ int   ti[128][3];
    __shared__ int   scnt16[NEXP];
    __shared__ int   gbase[NEXP];
    __shared__ float sred[NEXP][8];

    int tid = threadIdx.x;
    if (tid < NEXP) scnt16[tid] = 0;
    for (int i = tid; i < NEXP * DDIM; i += 128) {
        int d = i / NEXP, e = i % NEXP;
        WgT[e * DDIM + d] = Wg[i];
        WnT[e * DDIM + d] = Wn[i];
    }
    __syncthreads();

    int n = blockIdx.x * 128 + tid;

    float g[NEXP], ng[NEXP];
    #pragma unroll
    for (int e = 0; e < NEXP; e++) { g[e] = bg[e]; ng[e] = bn[e]; }

    const float4* x4 = (const float4*)(x + (size_t)n * DDIM);
    #pragma unroll 2
    for (int d4 = 0; d4 < DDIM / 4; d4++) {
        float4 xv = x4[d4];
        #pragma unroll
        for (int e = 0; e < NEXP; e++) {
            float4 a = ((const float4*)(WgT + e * DDIM))[d4];
            g[e]  += xv.x * a.x + xv.y * a.y + xv.z * a.z + xv.w * a.w;
            float4 b = ((const float4*)(WnT + e * DDIM))[d4];
            ng[e] += xv.x * b.x + xv.y * b.y + xv.z * b.z + xv.w * b.w;
        }
    }

    const float* nz = noise + (size_t)n * NEXP;
    #pragma unroll
    for (int e = 0; e < NEXP; e++) {
        float v = ng[e];
        float sp = (v > 20.f) ? v : log1pf(expf(v));
        g[e] = g[e] + nz[e] * sp;
    }

    float v0 = -INFINITY, v1 = -INFINITY, v2 = -INFINITY;
    int i0 = 0, i1 = 0, i2 = 0;
    #pragma unroll
    for (int e = 0; e < NEXP; e++) {
        float v = g[e];
        if (v > v0)      { v2 = v1; i2 = i1; v1 = v0; i1 = i0; v0 = v; i0 = e; }
        else if (v > v1) { v2 = v1; i2 = i1; v1 = v;  i1 = e; }
        else if (v > v2) { v2 = v;  i2 = e; }
    }

    float e1 = expf(v1 - v0), e2 = expf(v2 - v0);
    float s = 1.f + e1 + e2;
    float w0 = 1.f / s, w1 = e1 / s, w2 = e2 / s;

    int p0 = atomicAdd(&scnt16[i0], 1);
    int p1 = atomicAdd(&scnt16[i1], 1);
    int p2 = atomicAdd(&scnt16[i2], 1);

    tw[tid][0] = w0; tw[tid][1] = w1; tw[tid][2] = w2;
    ti[tid][0] = i0; ti[tid][1] = i1; ti[tid][2] = i2;

    {
        uint4 tk;
        tk.x = (unsigned)i0 | ((unsigned)i1 << 8) | ((unsigned)i2 << 16);
        tk.y = __float_as_uint(w0);
        tk.z = __float_as_uint(w1);
        tk.w = __float_as_uint(w2);
        g_topk[n] = tk;
    }
    __syncthreads();

    if (tid < NEXP) gbase[tid] = atomicAdd(&g_cnt[tid], scnt16[tid]);
    __syncthreads();

    {
        int q0 = gbase[i0] + p0;
        int q1 = gbase[i1] + p1;
        int q2 = gbase[i2] + p2;
        g_list[i0 * NTOK + q0] = ((unsigned)n << 2) | 0u;  g_wlist[i0 * NTOK + q0] = w0;
        g_list[i1 * NTOK + q1] = ((unsigned)n << 2) | 1u;  g_wlist[i1 * NTOK + q1] = w1;
        g_list[i2 * NTOK + q2] = ((unsigned)n << 2) | 2u;  g_wlist[i2 * NTOK + q2] = w2;
    }

    int base = blockIdx.x * 128;
    for (int i = tid; i < 128 * NEXP; i += 128) {
        int t = i >> 4, e = i & 15;
        float v = (e == ti[t][0]) ? tw[t][0]
                : (e == ti[t][1]) ? tw[t][1]
                : (e == ti[t][2]) ? tw[t][2] : 0.f;
        comb[(size_t)(base + t) * NEXP + e] = v;
    }

    {
        int e = tid & 15, j = tid >> 4;
        float ps = 0.f;
        int t0 = j * 16;
        #pragma unroll 4
        for (int t = t0; t < t0 + 16; t++) {
            if (ti[t][0] == e) ps += tw[t][0];
            if (ti[t][1] == e) ps += tw[t][1];
            if (ti[t][2] == e) ps += tw[t][2];
        }
        sred[e][j] = ps;
    }
    __syncthreads();
    if (tid < NEXP) {
        float s2 = 0.f;
        #pragma unroll
        for (int j = 0; j < 8; j++) s2 += sred[tid][j];
        g_part[blockIdx.x * NEXP + tid] = s2;
    }
}

// ---------------------------------------------------------------------------
// MoE GEMM: pure HMMA, double-buffered cp.async A gather (lean issue path:
// 2 threads per row, en loaded once, 8 cp.async each).
// grid (GEMM_GX, NEXP) x 256 (8 warps, 4M x 2N, 32x64 warp tiles), 2 CTAs/SM.
// ---------------------------------------------------------------------------
#define SM_A0  0
#define SM_A1  34816
#define SM_B   69632
#define SM_E0  104448
#define SM_E1  104960
#define SM_W0  105472
#define SM_W1  105984
#define SM_SZ  106496

__global__ void __launch_bounds__(256, 2) moe_gemm_kernel()
{
    extern __shared__ char smp[];
    uint32_t base = smem_u32(smp);

    int tid = threadIdx.x, wp = tid >> 5, ln = tid & 31;
    int e = blockIdx.y;
    int cnt = g_cnt[e];
    int ntile = (cnt + 127) >> 7;
    if ((int)blockIdx.x >= ntile) return;

    unsigned* entS[2] = { (unsigned*)(smp + SM_E0), (unsigned*)(smp + SM_E1) };
    float*    wSb[2]  = { (float*)(smp + SM_W0),    (float*)(smp + SM_W1) };
    const uint32_t smA[2] = { base + SM_A0, base + SM_A1 };

    // stage B via cp.async (34816 B = 2176 chunks)
    {
        const char* bsrc = (const char*)(g_Bh + (size_t)e * DDIM * KPAD);
        for (int i = tid; i < 2176; i += 256)
            cp_async16(base + SM_B + i * 16, bsrc + i * 16, 16);
    }

    int grow = tid >> 1;          // row 0..127 (2 threads per row)
    int ghalf = tid & 1;          // which 8-chunk half of the row

    // issue A gather for tile t into buffer b
    auto issue_tile = [&](int t, int b) {
        int gi = (t << 7) + grow;
        unsigned en = 0xFFFFFFFFu;
        if (gi < cnt) en = g_list[e * NTOK + gi];
        unsigned tok = (en != 0xFFFFFFFFu) ? (en >> 2) : 0u;
        uint32_t sz = (en != 0xFFFFFFFFu) ? 16u : 0u;
        const char* src = (const char*)(g_xh + (size_t)tok * DDIM) + ghalf * 128;
        uint32_t dst = smA[b] + (uint32_t)grow * ROWB + (uint32_t)ghalf * 128;
        #pragma unroll
        for (int j = 0; j < 8; j++)
            cp_async16(dst + j * 16, src + j * 16, sz);
        if (ghalf == 0) entS[b][grow] = en;
        else            wSb[b][grow] = (gi < cnt) ? g_wlist[e * NTOK + gi] : 0.f;
    };

    int mrow = (wp & 3) * 32;
    int ncol = (wp >> 2) * 64;
    uint32_t a_off = (uint32_t)(mrow + (ln & 15)) * ROWB + ((ln >> 4) << 4);
    uint32_t b_off = (uint32_t)(ncol + (ln & 7) + ((ln >> 4) << 3)) * ROWB + (((ln >> 3) & 1) << 4);

    issue_tile(blockIdx.x, 0);
    CP_COMMIT();

    int buf = 0;
    for (int t = blockIdx.x; t < ntile; t += GEMM_GX) {
        int tn = t + GEMM_GX;
        if (tn < ntile) {
            issue_tile(tn, buf ^ 1);
            CP_COMMIT();
            asm volatile("cp.async.wait_group 1;" ::: "memory");
        } else {
            asm volatile("cp.async.wait_group 0;" ::: "memory");
        }
        __syncthreads();

        float c[2][8][4];
        #pragma unroll
        for (int i = 0; i < 2; i++)
            #pragma unroll
            for (int j = 0; j < 8; j++)
                #pragma unroll
                for (int q = 0; q < 4; q++) c[i][j][q] = 0.f;

        uint32_t ab = smA[buf] + a_off;
        uint32_t bb = base + SM_B + b_off;
        #pragma unroll
        for (int kk = 0; kk < 8; kk++) {
            uint32_t kb = (uint32_t)kk * 32;
            uint32_t a0, a1, a2, a3, a4, a5, a6, a7;
            LDSM_X4(a0, a1, a2, a3, ab + kb);
            LDSM_X4(a4, a5, a6, a7, ab + 16 * ROWB + kb);
            #pragma unroll
            for (int nw = 0; nw < 4; nw++) {
                uint32_t b0, b1, b2, b3;
                LDSM_X4(b0, b1, b2, b3, bb + (uint32_t)nw * 16 * ROWB + kb);
                mma16816(c[0][nw * 2 + 0], a0, a1, a2, a3, b0, b1);
                mma16816(c[0][nw * 2 + 1], a0, a1, a2, a3, b2, b3);
                mma16816(c[1][nw * 2 + 0], a4, a5, a6, a7, b0, b1);
                mma16816(c[1][nw * 2 + 1], a4, a5, a6, a7, b2, b3);
            }
        }

        // epilogue: scale by routing weight, direct fp16 stores
        {
            int gid = ln >> 2, tig = ln & 3;
            #pragma unroll
            for (int mt = 0; mt < 2; mt++) {
                int r0 = mrow + mt * 16 + gid;
                int r1 = r0 + 8;
                unsigned e0 = entS[buf][r0], e1 = entS[buf][r1];
                float wa = wSb[buf][r0], wb = wSb[buf][r1];
                __half* y0 = g_ybuf + ((size_t)(e0 >> 2) * 3 + (e0 & 3u)) * DDIM;
                __half* y1 = g_ybuf + ((size_t)(e1 >> 2) * 3 + (e1 & 3u)) * DDIM;
                #pragma unroll
                for (int nt = 0; nt < 8; nt++) {
                    int col = ncol + nt * 8 + tig * 2;
                    if (e0 != 0xFFFFFFFFu) {
                        __half2 hv;
                        hv.x = __float2half(c[mt][nt][0] * wa);
                        hv.y = __float2half(c[mt][nt][1] * wa);
                        *(__half2*)(y0 + col) = hv;
                    }
                    if (e1 != 0xFFFFFFFFu) {
                        __half2 hv;
                        hv.x = __float2half(c[mt][nt][2] * wb);
                        hv.y = __float2half(c[mt][nt][3] * wb);
                        *(__half2*)(y1 + col) = hv;
                    }
                }
            }
        }
        __syncthreads();   // protect buffer reuse by next issue
        buf ^= 1;
    }
}

// ---------------------------------------------------------------------------
// Combine (+ fused loss in the extra block). grid 4097 x 256.
// ---------------------------------------------------------------------------
__global__ void __launch_bounds__(256) combine_kernel(
    const float* __restrict__ be, const float* __restrict__ part,
    float* __restrict__ logits, float* __restrict__ out_loss)
{
    int tid = threadIdx.x;

    if (blockIdx.x == 4096) {
        // ---- loss block ----
        __shared__ float red[NEXP][17];
        int e = tid >> 4, j = tid & 15;
        float s = 0.f;
        for (int k = 0; k < 32; k++) s += part[(j * 32 + k) * NEXP + e];
        red[e][j] = s;
        __syncthreads();
        if (tid < NEXP) {
            float t = 0.f;
            #pragma unroll
            for (int q = 0; q < 16; q++) t += red[tid][q];
            red[tid][16] = t;
        }
        __syncthreads();
        if (tid == 0) {
            float mean = 0.f;
            for (int e2 = 0; e2 < NEXP; e2++) mean += red[e2][16];
            mean /= (float)NEXP;
            float var = 0.f;
            for (int e2 = 0; e2 < NEXP; e2++) {
                float d = red[e2][16] - mean;
                var += d * d;
            }
            var /= (float)(NEXP - 1);
            out_loss[0] = var / (mean * mean);
        }
        return;
    }

    __shared__ float beS[NEXP][DDIM];
    for (int i = tid; i < NEXP * DDIM; i += 256) beS[i >> 7][i & 127] = be[i];
    __syncthreads();

    size_t idx = (size_t)blockIdx.x * 256 + tid;
    int n = (int)(idx >> 4), c8 = (int)(idx & 15);
    int col = c8 * 8;

    uint4 tk = g_topk[n];
    int i0 = tk.x & 255, i1 = (tk.x >> 8) & 255, i2 = (tk.x >> 16) & 255;
    float w0 = __uint_as_float(tk.y);
    float w1 = __uint_as_float(tk.z);
    float w2 = __uint_as_float(tk.w);

    const __half* y = g_ybuf + (size_t)n * 3 * DDIM;
    uint4 p = *(const uint4*)(y + col);
    uint4 q = *(const uint4*)(y + DDIM + col);
    uint4 r = *(const uint4*)(y + 2 * DDIM + col);

    float out[8];
    {
        const uint32_t* pp = (const uint32_t*)&p;
        const uint32_t* qq = (const uint32_t*)&q;
        const uint32_t* rr = (const uint32_t*)&r;
        #pragma unroll
        for (int j = 0; j < 4; j++) {
            float2 a = __half22float2(*(__half2*)&pp[j]);
            float2 b = __half22float2(*(__half2*)&qq[j]);
            float2 d = __half22float2(*(__half2*)&rr[j]);
            out[2 * j + 0] = a.x + b.x + d.x;
            out[2 * j + 1] = a.y + b.y + d.y;
        }
    }
    #pragma unroll
    for (int half = 0; half < 2; half++) {
        int c4 = col + half * 4;
        const float4 b0 = *(const float4*)(&beS[i0][c4]);
        const float4 b1 = *(const float4*)(&beS[i1][c4]);
        const float4 b2 = *(const float4*)(&beS[i2][c4]);
        float4 a;
        a.x = out[half * 4 + 0] + w0 * b0.x + w1 * b1.x + w2 * b2.x;
        a.y = out[half * 4 + 1] + w0 * b0.y + w1 * b1.y + w2 * b2.y;
        a.z = out[half * 4 + 2] + w0 * b0.z + w1 * b1.z + w2 * b2.z;
        a.w = out[half * 4 + 3] + w0 * b0.w + w1 * b1.w + w2 * b2.w;
        *(float4*)(logits + (size_t)n * DDIM + c4) = a;
    }
}

// ---------------------------------------------------------------------------
extern "C" void kernel_launch(void* const* d_in, const int* in_sizes, int n_in,
                              void* d_out, int out_size)
{
    const float* x     = (const float*)d_in[0];
    const float* noise = (const float*)d_in[1];
    const float* Wg    = (const float*)d_in[2];
    const float* bg    = (const float*)d_in[3];
    const float* Wn    = (const float*)d_in[4];
    const float* bn    = (const float*)d_in[5];
    const float* We    = (const float*)d_in[6];
    const float* be    = (const float*)d_in[7];

    float* out    = (float*)d_out;
    float* logits = out;
    float* lossp  = out + (size_t)NTOK * DDIM;
    float* comb   = lossp + 1;

    float* part;  cudaGetSymbolAddress((void**)&part, g_part);

    prep_kernel<<<8192 + 64, 256>>>(x, We);              // (1) x->fp16, B images, zero g_cnt

    gating_kernel<<<NTOK / 128, 128>>>(x, noise, Wg, bg, Wn, bn, comb);  // (2)

    cudaFuncSetAttribute(moe_gemm_kernel,
                         cudaFuncAttributeMaxDynamicSharedMemorySize, SM_SZ);
    moe_gemm_kernel<<<dim3(GEMM_GX, NEXP), 256, SM_SZ>>>();  // (3) <- profiled

    combine_kernel<<<4097, 256>>>(be, part, logits, lossp);  // (4) + fused loss

    (void)in_sizes; (void)n_in; (void)out_size;
}

// round 13
// speedup vs baseline: 1.0426x; 1.0426x over previous
#include <cuda_runtime.h>
#include <cuda_fp16.h>
#include <math.h>
#include <stdint.h>

#define NTOK 65536
#define DDIM 128
#define NEXP 16
#define TOPK 3

#define KPAD 136              // fp16 per padded row
#define ROWB 272              // bytes per padded row (16B-aligned, bank stride 4)
#define GEMM_GX 18            // 16*18=288 CTAs ~= one wave at 2 CTAs/SM

// ---------------------------------------------------------------------------
// Device globals
// ---------------------------------------------------------------------------
__device__ int      g_cnt[NEXP];
__device__ unsigned g_list[NEXP * NTOK];                 // (token<<2)|slot
__device__ float    g_wlist[NEXP * NTOK];
__device__ __half   g_Bh[NEXP * DDIM * KPAD];            // fp16 We^T, padded rows
__device__ __half   g_xh[(size_t)NTOK * DDIM];           // fp16 image of x (16MB)
__device__ __half   g_ybuf[(size_t)NTOK * TOPK * DDIM];  // fp16 partials (24MB)
__device__ uint4    g_topk[NTOK];
__device__ float    g_part[512 * NEXP];

// ---------------------------------------------------------------------------
// helpers
// ---------------------------------------------------------------------------
__device__ __forceinline__ uint32_t smem_u32(const void* p) {
    uint32_t a;
    asm("{ .reg .u64 t; cvta.to.shared.u64 t, %1; cvt.u32.u64 %0, t; }" : "=r"(a) : "l"(p));
    return a;
}

#define MBAR_INIT(mb, c)  asm volatile("mbarrier.init.shared.b64 [%0], %1;" \
                                       :: "r"(mb), "r"((uint32_t)(c)) : "memory")
#define MBAR_EXPECT(mb, tx) asm volatile("mbarrier.arrive.expect_tx.shared.b64 _, [%0], %1;" \
                                         :: "r"(mb), "r"((uint32_t)(tx)) : "memory")

__device__ __forceinline__ void bulk_g2s(uint32_t dst, const void* src,
                                         uint32_t bytes, uint32_t mbar) {
    asm volatile(
        "cp.async.bulk.shared::cluster.global.mbarrier::complete_tx::bytes [%0], [%1], %2, [%3];"
        :: "r"(dst), "l"(src), "r"(bytes), "r"(mbar) : "memory");
}

__device__ __forceinline__ void mbar_wait(uint32_t mb, uint32_t parity) {
    uint32_t done;
    asm volatile(
        "{\n\t.reg .pred p;\n\t"
        "mbarrier.try_wait.parity.acquire.cta.shared::cta.b64 p, [%1], %2;\n\t"
        "selp.b32 %0, 1, 0, p;\n\t}"
        : "=r"(done) : "r"(mb), "r"(parity) : "memory");
    if (!done) {
        asm volatile(
            "{\n\t.reg .pred P1;\n\t"
            "WL_%=:\n\t"
            "mbarrier.try_wait.parity.acquire.cta.shared::cta.b64 P1, [%0], %1, 0x989680;\n\t"
            "@P1 bra.uni WD_%=;\n\t"
            "bra.uni WL_%=;\n\t"
            "WD_%=:\n\t}"
            :: "r"(mb), "r"(parity) : "memory");
    }
}

#define LDSM_X4(r0, r1, r2, r3, addr) \
    asm volatile("ldmatrix.sync.aligned.m8n8.x4.shared.b16 {%0,%1,%2,%3}, [%4];" \
                 : "=r"(r0), "=r"(r1), "=r"(r2), "=r"(r3) : "r"(addr))

__device__ __forceinline__ void mma16816(float* c,
    uint32_t a0, uint32_t a1, uint32_t a2, uint32_t a3, uint32_t b0, uint32_t b1)
{
    asm volatile(
        "mma.sync.aligned.m16n8k16.row.col.f32.f16.f16.f32 "
        "{%0,%1,%2,%3}, {%4,%5,%6,%7}, {%8,%9}, {%0,%1,%2,%3};"
        : "+f"(c[0]), "+f"(c[1]), "+f"(c[2]), "+f"(c[3])
        : "r"(a0), "r"(a1), "r"(a2), "r"(a3), "r"(b0), "r"(b1));
}

// ---------------------------------------------------------------------------
// prep_xh: fp16 image of x; zeroes g_cnt. grid 8192 x 256
// ---------------------------------------------------------------------------
__global__ void __launch_bounds__(256) prep_xh_kernel(const float* __restrict__ x)
{
    if (blockIdx.x == 0 && threadIdx.x < NEXP) g_cnt[threadIdx.x] = 0;
    size_t i = (size_t)blockIdx.x * 256 + threadIdx.x;   // over NTOK*DDIM/4
    float4 v = ((const float4*)x)[i];
    __half2 h0, h1;
    h0.x = __float2half(v.x); h0.y = __float2half(v.y);
    h1.x = __float2half(v.z); h1.y = __float2half(v.w);
    uint2 st;
    st.x = *(uint32_t*)&h0;
    st.y = *(uint32_t*)&h1;
    *(uint2*)(g_xh + i * 4) = st;
}

// ---------------------------------------------------------------------------
// prepB: fp16 padded image of We^T ([e][n][k], n=0..127). grid (16,4) x 256
// ---------------------------------------------------------------------------
__global__ void __launch_bounds__(256) prepB_kernel(const float* __restrict__ We)
{
    int e = blockIdx.x;
    const float* W = We + (size_t)e * DDIM * DDIM;
    __half* dst = g_Bh + (size_t)e * DDIM * KPAD;
    int i0 = blockIdx.y * 2048 + threadIdx.x;
    for (int i = i0; i < (blockIdx.y + 1) * 2048; i += 256) {
        int n = i >> 6, kp = i & 63, k = kp * 2;
        __half2 hp;
        hp.x = __float2half(W[k * DDIM + n]);
        hp.y = __float2half(W[(k + 1) * DDIM + n]);
        *(__half2*)(dst + n * KPAD + k) = hp;
    }
}

// ---------------------------------------------------------------------------
// Gating (unchanged from R11)
// ---------------------------------------------------------------------------
__global__ void __launch_bounds__(128) gating_kernel(
    const float* __restrict__ x, const float* __restrict__ noise,
    const float* __restrict__ Wg, const float* __restrict__ bg,
    const float* __restrict__ Wn, const float* __restrict__ bn,
    float* __restrict__ comb)
{
    __shared__ float WgT[NEXP * DDIM];
    __shared__ float WnT[NEXP * DDIM];
    __shared__ float tw[128][3];
    __shared__ int   ti[128][3];
    __shared__ int   scnt16[NEXP];
    __shared__ int   gbase[NEXP];
    __shared__ float sred[NEXP][8];

    int tid = threadIdx.x;
    if (tid < NEXP) scnt16[tid] = 0;
    for (int i = tid; i < NEXP * DDIM; i += 128) {
        int d = i / NEXP, e = i % NEXP;
        WgT[e * DDIM + d] = Wg[i];
        WnT[e * DDIM + d] = Wn[i];
    }
    __syncthreads();

    int n = blockIdx.x * 128 + tid;

    float g[NEXP], ng[NEXP];
    #pragma unroll
    for (int e = 0; e < NEXP; e++) { g[e] = bg[e]; ng[e] = bn[e]; }

    const float4* x4 = (const float4*)(x + (size_t)n * DDIM);
    #pragma unroll 2
    for (int d4 = 0; d4 < DDIM / 4; d4++) {
        float4 xv = x4[d4];
        #pragma unroll
        for (int e = 0; e < NEXP; e++) {
            float4 a = ((const float4*)(WgT + e * DDIM))[d4];
            g[e]  += xv.x * a.x + xv.y * a.y + xv.z * a.z + xv.w * a.w;
            float4 b = ((const float4*)(WnT + e * DDIM))[d4];
            ng[e] += xv.x * b.x + xv.y * b.y + xv.z * b.z + xv.w * b.w;
        }
    }

    const float* nz = noise + (size_t)n * NEXP;
    #pragma unroll
    for (int e = 0; e < NEXP; e++) {
        float v = ng[e];
        float sp = (v > 20.f) ? v : log1pf(expf(v));
        g[e] = g[e] + nz[e] * sp;
    }

    float v0 = -INFINITY, v1 = -INFINITY, v2 = -INFINITY;
    int i0 = 0, i1 = 0, i2 = 0;
    #pragma unroll
    for (int e = 0; e < NEXP; e++) {
        float v = g[e];
        if (v > v0)      { v2 = v1; i2 = i1; v1 = v0; i1 = i0; v0 = v; i0 = e; }
        else if (v > v1) { v2 = v1; i2 = i1; v1 = v;  i1 = e; }
        else if (v > v2) { v2 = v;  i2 = e; }
    }

    float e1 = expf(v1 - v0), e2 = expf(v2 - v0);
    float s = 1.f + e1 + e2;
    float w0 = 1.f / s, w1 = e1 / s, w2 = e2 / s;

    int p0 = atomicAdd(&scnt16[i0], 1);
    int p1 = atomicAdd(&scnt16[i1], 1);
    int p2 = atomicAdd(&scnt16[i2], 1);

    tw[tid][0] = w0; tw[tid][1] = w1; tw[tid][2] = w2;
    ti[tid][0] = i0; ti[tid][1] = i1; ti[tid][2] = i2;

    {
        uint4 tk;
        tk.x = (unsigned)i0 | ((unsigned)i1 << 8) | ((unsigned)i2 << 16);
        tk.y = __float_as_uint(w0);
        tk.z = __float_as_uint(w1);
        tk.w = __float_as_uint(w2);
        g_topk[n] = tk;
    }
    __syncthreads();

    if (tid < NEXP) gbase[tid] = atomicAdd(&g_cnt[tid], scnt16[tid]);
    __syncthreads();

    {
        int q0 = gbase[i0] + p0;
        int q1 = gbase[i1] + p1;
        int q2 = gbase[i2] + p2;
        g_list[i0 * NTOK + q0] = ((unsigned)n << 2) | 0u;  g_wlist[i0 * NTOK + q0] = w0;
        g_list[i1 * NTOK + q1] = ((unsigned)n << 2) | 1u;  g_wlist[i1 * NTOK + q1] = w1;
        g_list[i2 * NTOK + q2] = ((unsigned)n << 2) | 2u;  g_wlist[i2 * NTOK + q2] = w2;
    }

    int base = blockIdx.x * 128;
    for (int i = tid; i < 128 * NEXP; i += 128) {
        int t = i >> 4, e = i & 15;
        float v = (e == ti[t][0]) ? tw[t][0]
                : (e == ti[t][1]) ? tw[t][1]
                : (e == ti[t][2]) ? tw[t][2] : 0.f;
        comb[(size_t)(base + t) * NEXP + e] = v;
    }

    {
        int e = tid & 15, j = tid >> 4;
        float ps = 0.f;
        int t0 = j * 16;
        #pragma unroll 4
        for (int t = t0; t < t0 + 16; t++) {
            if (ti[t][0] == e) ps += tw[t][0];
            if (ti[t][1] == e) ps += tw[t][1];
            if (ti[t][2] == e) ps += tw[t][2];
        }
        sred[e][j] = ps;
    }
    __syncthreads();
    if (tid < NEXP) {
        float s2 = 0.f;
        #pragma unroll
        for (int j = 0; j < 8; j++) s2 += sred[tid][j];
        g_part[blockIdx.x * NEXP + tid] = s2;
    }
}

// ---------------------------------------------------------------------------
// MoE GEMM: pure HMMA, double-buffered A gather via cp.async.bulk + mbarrier.
// grid (GEMM_GX, NEXP) x 256 (8 warps, 4M x 2N, 32x64 warp tiles), 2 CTAs/SM.
// smem: A0[0,34816) A1[34816,69632) B[69632,104448)
//       ent0/ent1/w0/w1 [104448..106496)  mbar x3 [106496,106520)
// ---------------------------------------------------------------------------
#define SM_A0  0
#define SM_A1  34816
#define SM_B   69632
#define SM_E0  104448
#define SM_E1  104960
#define SM_W0  105472
#define SM_W1  105984
#define SM_MB  106496
#define SM_SZ  106624

__global__ void __launch_bounds__(256, 2) moe_gemm_kernel()
{
    extern __shared__ char smp[];
    uint32_t base = smem_u32(smp);

    int tid = threadIdx.x, wp = tid >> 5, ln = tid & 31;
    int e = blockIdx.y;
    int cnt = g_cnt[e];
    int ntile = (cnt + 127) >> 7;
    if ((int)blockIdx.x >= ntile) return;

    unsigned* entS[2] = { (unsigned*)(smp + SM_E0), (unsigned*)(smp + SM_E1) };
    float*    wSb[2]  = { (float*)(smp + SM_W0),    (float*)(smp + SM_W1) };
    const uint32_t smA[2] = { base + SM_A0, base + SM_A1 };
    const uint32_t mb[2]  = { base + SM_MB, base + SM_MB + 8 };
    const uint32_t mbB    = base + SM_MB + 16;

    if (tid == 0) {
        MBAR_INIT(mb[0], 128);
        MBAR_INIT(mb[1], 128);
        MBAR_INIT(mbB, 1);
    }
    __syncthreads();   // init visible before any arrivals

    // B: one bulk copy (34816 B)
    if (tid == 0) {
        MBAR_EXPECT(mbB, 34816);
        bulk_g2s(base + SM_B, g_Bh + (size_t)e * DDIM * KPAD, 34816, mbB);
    }

    // issue A gather for tile t into buffer b: 1 thread per row, 1 bulk per row
    auto issue_tile = [&](int t, int b) {
        if (tid < 128) {
            int gi = (t << 7) + tid;
            unsigned en = 0xFFFFFFFFu;
            float w = 0.f;
            if (gi < cnt) {
                en = g_list[e * NTOK + gi];
                w  = g_wlist[e * NTOK + gi];
            }
            entS[b][tid] = en;
            wSb[b][tid]  = w;
            if (en != 0xFFFFFFFFu) {
                MBAR_EXPECT(mb[b], 256u);
                bulk_g2s(smA[b] + (uint32_t)tid * ROWB,
                         g_xh + (size_t)(en >> 2) * DDIM, 256, mb[b]);
            } else {
                MBAR_EXPECT(mb[b], 0u);   // arrive only; stale A rows never stored
            }
        }
    };

    int mrow = (wp & 3) * 32;
    int ncol = (wp >> 2) * 64;
    uint32_t a_off = (uint32_t)(mrow + (ln & 15)) * ROWB + ((ln >> 4) << 4);
    uint32_t b_off = (uint32_t)(ncol + (ln & 7) + ((ln >> 4) << 3)) * ROWB + (((ln >> 3) & 1) << 4);

    issue_tile(blockIdx.x, 0);

    int ph[2] = { 0, 0 };
    int buf = 0;
    bool needB = true;
    for (int t = blockIdx.x; t < ntile; t += GEMM_GX) {
        int tn = t + GEMM_GX;
        if (tn < ntile) issue_tile(tn, buf ^ 1);

        mbar_wait(mb[buf], (uint32_t)ph[buf]);
        ph[buf] ^= 1;
        if (needB) { mbar_wait(mbB, 0); needB = false; }
        __syncthreads();

        // ---------------- MMA from buffer `buf` ----------------
        float c[2][8][4];
        #pragma unroll
        for (int i = 0; i < 2; i++)
            #pragma unroll
            for (int j = 0; j < 8; j++)
                #pragma unroll
                for (int q = 0; q < 4; q++) c[i][j][q] = 0.f;

        uint32_t ab = smA[buf] + a_off;
        uint32_t bb = base + SM_B + b_off;
        #pragma unroll
        for (int kk = 0; kk < 8; kk++) {
            uint32_t kb = (uint32_t)kk * 32;
            uint32_t a0, a1, a2, a3, a4, a5, a6, a7;
            LDSM_X4(a0, a1, a2, a3, ab + kb);
            LDSM_X4(a4, a5, a6, a7, ab + 16 * ROWB + kb);
            #pragma unroll
            for (int nw = 0; nw < 4; nw++) {
                uint32_t b0, b1, b2, b3;
                LDSM_X4(b0, b1, b2, b3, bb + (uint32_t)nw * 16 * ROWB + kb);
                mma16816(c[0][nw * 2 + 0], a0, a1, a2, a3, b0, b1);
                mma16816(c[0][nw * 2 + 1], a0, a1, a2, a3, b2, b3);
                mma16816(c[1][nw * 2 + 0], a4, a5, a6, a7, b0, b1);
                mma16816(c[1][nw * 2 + 1], a4, a5, a6, a7, b2, b3);
            }
        }

        // epilogue: scale by routing weight, direct fp16 stores
        {
            int gid = ln >> 2, tig = ln & 3;
            #pragma unroll
            for (int mt = 0; mt < 2; mt++) {
                int r0 = mrow + mt * 16 + gid;
                int r1 = r0 + 8;
                unsigned e0 = entS[buf][r0], e1 = entS[buf][r1];
                float wa = wSb[buf][r0], wb = wSb[buf][r1];
                __half* y0 = g_ybuf + ((size_t)(e0 >> 2) * 3 + (e0 & 3u)) * DDIM;
                __half* y1 = g_ybuf + ((size_t)(e1 >> 2) * 3 + (e1 & 3u)) * DDIM;
                #pragma unroll
                for (int nt = 0; nt < 8; nt++) {
                    int col = ncol + nt * 8 + tig * 2;
                    if (e0 != 0xFFFFFFFFu) {
                        __half2 hv;
                        hv.x = __float2half(c[mt][nt][0] * wa);
                        hv.y = __float2half(c[mt][nt][1] * wa);
                        *(__half2*)(y0 + col) = hv;
                    }
                    if (e1 != 0xFFFFFFFFu) {
                        __half2 hv;
                        hv.x = __float2half(c[mt][nt][2] * wb);
                        hv.y = __float2half(c[mt][nt][3] * wb);
                        *(__half2*)(y1 + col) = hv;
                    }
                }
            }
        }
        __syncthreads();   // protect buffer reuse by next issue
        buf ^= 1;
    }
}

// ---------------------------------------------------------------------------
// Combine: thread owns 8 cols of one token. grid 4096 x 256. (R11 version)
// ---------------------------------------------------------------------------
__global__ void __launch_bounds__(256) combine_kernel(
    const float* __restrict__ be, float* __restrict__ logits)
{
    __shared__ float beS[NEXP][DDIM];

    int tid = threadIdx.x;
    for (int i = tid; i < NEXP * DDIM; i += 256) beS[i >> 7][i & 127] = be[i];
    __syncthreads();

    size_t idx = (size_t)blockIdx.x * 256 + tid;
    int n = (int)(idx >> 4), c8 = (int)(idx & 15);
    int col = c8 * 8;

    uint4 tk = g_topk[n];
    int i0 = tk.x & 255, i1 = (tk.x >> 8) & 255, i2 = (tk.x >> 16) & 255;
    float w0 = __uint_as_float(tk.y);
    float w1 = __uint_as_float(tk.z);
    float w2 = __uint_as_float(tk.w);

    const __half* y = g_ybuf + (size_t)n * 3 * DDIM;
    uint4 p = *(const uint4*)(y + col);
    uint4 q = *(const uint4*)(y + DDIM + col);
    uint4 r = *(const uint4*)(y + 2 * DDIM + col);

    float out[8];
    {
        const uint32_t* pp = (const uint32_t*)&p;
        const uint32_t* qq = (const uint32_t*)&q;
        const uint32_t* rr = (const uint32_t*)&r;
        #pragma unroll
        for (int j = 0; j < 4; j++) {
            float2 a = __half22float2(*(__half2*)&pp[j]);
            float2 b = __half22float2(*(__half2*)&qq[j]);
            float2 d = __half22float2(*(__half2*)&rr[j]);
            out[2 * j + 0] = a.x + b.x + d.x;
            out[2 * j + 1] = a.y + b.y + d.y;
        }
    }
    #pragma unroll
    for (int half = 0; half < 2; half++) {
        int c4 = col + half * 4;
        const float4 b0 = *(const float4*)(&beS[i0][c4]);
        const float4 b1 = *(const float4*)(&beS[i1][c4]);
        const float4 b2 = *(const float4*)(&beS[i2][c4]);
        float4 a;
        a.x = out[half * 4 + 0] + w0 * b0.x + w1 * b1.x + w2 * b2.x;
        a.y = out[half * 4 + 1] + w0 * b0.y + w1 * b1.y + w2 * b2.y;
        a.z = out[half * 4 + 2] + w0 * b0.z + w1 * b1.z + w2 * b2.z;
        a.w = out[half * 4 + 3] + w0 * b0.w + w1 * b1.w + w2 * b2.w;
        *(float4*)(logits + (size_t)n * DDIM + c4) = a;
    }
}

// ---------------------------------------------------------------------------
// Loss (R11 version)
// ---------------------------------------------------------------------------
__global__ void loss_kernel(const float* __restrict__ part, float* __restrict__ out_loss)
{
    __shared__ float red[NEXP][17];
    int tid = threadIdx.x;
    int e = tid >> 4, j = tid & 15;
    float s = 0.f;
    for (int k = 0; k < 32; k++) s += part[(j * 32 + k) * NEXP + e];
    red[e][j] = s;
    __syncthreads();
    if (tid < NEXP) {
        float t = 0.f;
        #pragma unroll
        for (int q = 0; q < 16; q++) t += red[tid][q];
        red[tid][16] = t;
    }
    __syncthreads();
    if (tid == 0) {
        float mean = 0.f;
        for (int e2 = 0; e2 < NEXP; e2++) mean += red[e2][16];
        mean /= (float)NEXP;
        float var = 0.f;
        for (int e2 = 0; e2 < NEXP; e2++) {
            float d = red[e2][16] - mean;
            var += d * d;
        }
        var /= (float)(NEXP - 1);
        out_loss[0] = var / (mean * mean);
    }
}

// ---------------------------------------------------------------------------
extern "C" void kernel_launch(void* const* d_in, const int* in_sizes, int n_in,
                              void* d_out, int out_size)
{
    const float* x     = (const float*)d_in[0];
    const float* noise = (const float*)d_in[1];
    const float* Wg    = (const float*)d_in[2];
    const float* bg    = (const float*)d_in[3];
    const float* Wn    = (const float*)d_in[4];
    const float* bn    = (const float*)d_in[5];
    const float* We    = (const float*)d_in[6];
    const float* be    = (const float*)d_in[7];

    float* out    = (float*)d_out;
    float* logits = out;
    float* lossp  = out + (size_t)NTOK * DDIM;
    float* comb   = lossp + 1;

    float* part;  cudaGetSymbolAddress((void**)&part, g_part);

    prep_xh_kernel<<<NTOK * DDIM / 4 / 256, 256>>>(x);   // (1) + zero g_cnt

    prepB_kernel<<<dim3(NEXP, 4), 256>>>(We);            // (2)

    gating_kernel<<<NTOK / 128, 128>>>(x, noise, Wg, bg, Wn, bn, comb);  // (3)

    cudaFuncSetAttribute(moe_gemm_kernel,
                         cudaFuncAttributeMaxDynamicSharedMemorySize, SM_SZ);
    moe_gemm_kernel<<<dim3(GEMM_GX, NEXP), 256, SM_SZ>>>();  // (4) <- profiled slot

    loss_kernel<<<1, 256>>>(part, lossp);                // (5)

    combine_kernel<<<NTOK * 16 / 256, 256>>>(be, logits);  // (6)

    (void)in_sizes; (void)n_in; (void)out_size;
}